// round 8
// baseline (speedup 1.0000x reference)
#include <cuda_runtime.h>
#include <math.h>

#define Nn 8192
#define Dn 2048
#define Kn 256
#define NBLK 148
#define ROWS_PB 14            // 148 * 14 = 2072 >= 2048

typedef unsigned long long ull;

// ---------------- f32x2 packed FMA helpers (Blackwell FFMA2) ----------------
__device__ __forceinline__ ull splat2(float s) {
    ull d;
    asm("mov.b64 %0, {%1, %1};" : "=l"(d) : "r"(__float_as_uint(s)));
    return d;
}
__device__ __forceinline__ void fma2(ull& d, ull a, ull b) {
    asm("fma.rn.f32x2 %0, %1, %2, %0;" : "+l"(d) : "l"(a), "l"(b));
}

// ---------------- device scratch (static: no allocation allowed) ----------------
__device__ float g_C[(size_t)Dn * Dn];     // 16 MB  C = x^T x
__device__ float g_Vt[(size_t)Kn * Dn];    // Vt[k][d] = V0[d][k]
__device__ float g_VnT[(size_t)Dn * Kn];   // VnT[d][j] = vn_j[d] (for gemmOut)
__device__ float g_a[Dn];
__device__ float g_c1[2][Kn];              // vn_j . v_{k}   (double buffered)
__device__ float g_c3[2][Kn];              // vn_j . u       (double buffered)
__device__ float g_g[Kn];                  // w_j . b
__device__ float g_d0[Kn];
__device__ float g_dn2[2];
__device__ float g_uv[2];
// barrier v4 state: 8 arrival counters 1KB apart (distinct LTS slices),
// one clean release word, one done counter.
__device__ __align__(128) unsigned g_cnt[8 * 256];
__device__ __align__(128) unsigned g_rel;
__device__ __align__(128) unsigned g_done;

// ---------------- grid barrier v4: sharded arrivals + idle-block master -------
// All NBLK CTAs co-resident (1 CTA/SM). Single-counter barriers are floored at
// ~148*27 cyc of L2 atomic drain; sharding arrivals over 8 counters on distinct
// LTS slices cuts the drain ~8x. Block NBLK-1 owns ZERO rows (idle in every
// phase), so it serves as the dedicated master: it acquire-polls the 8 counters
// and publishes to g_rel; everyone else polls only the clean g_rel line.
__device__ __forceinline__ void gbar(unsigned& gen, int bid) {
    ++gen;
    __syncthreads();
    if (threadIdx.x == 0) {
        asm volatile("red.release.gpu.global.add.u32 [%0], 1;"
                     :: "l"(&g_cnt[(bid & 7) * 256]) : "memory");
        if (bid == NBLK - 1) {
            // 148 = 19*4 + 18*4 : counters 0..3 expect 19/gen, 4..7 expect 18/gen
            const unsigned t19 = gen * 19u, t18 = gen * 18u;
            unsigned v[8];
            bool ok;
            do {
                #pragma unroll
                for (int c = 0; c < 8; ++c)
                    asm volatile("ld.acquire.gpu.global.u32 %0, [%1];"
                                 : "=r"(v[c]) : "l"(&g_cnt[c * 256]) : "memory");
                ok = true;
                #pragma unroll
                for (int c = 0; c < 8; ++c)
                    ok &= ((int)(v[c] - (c < 4 ? t19 : t18)) >= 0);
            } while (!ok);
            asm volatile("st.release.gpu.global.u32 [%0], %1;"
                         :: "l"(&g_rel), "r"(gen) : "memory");
        } else {
            unsigned v;
            do {
                asm volatile("ld.acquire.gpu.global.u32 %0, [%1];"
                             : "=r"(v) : "l"(&g_rel) : "memory");
            } while ((int)(v - gen) < 0);
        }
    }
    __syncthreads();
}

// ---------------- prep: transpose V0 -> Vt, per-column norms d0 ----------------
__global__ void __launch_bounds__(256) prep_kernel(const float* __restrict__ V0) {
    __shared__ float sb[8];
    int k = blockIdx.x;
    float s = 0.f;
    for (int d = threadIdx.x; d < Dn; d += 256) {
        float v = V0[(size_t)d * Kn + k];
        g_Vt[(size_t)k * Dn + d] = v;
        s += v * v;
    }
    #pragma unroll
    for (int o = 16; o; o >>= 1) s += __shfl_down_sync(~0u, s, o);
    if ((threadIdx.x & 31) == 0) sb[threadIdx.x >> 5] = s;
    __syncthreads();
    if (threadIdx.x == 0) {
        float t = 0.f;
        #pragma unroll
        for (int w = 0; w < 8; ++w) t += sb[w];
        g_d0[k] = sqrtf(t);
    }
}

// ---------------- C = x^T x (symmetric, double-buffered, f32x2) ----------------
__global__ void __launch_bounds__(256) gemmC_kernel(const float* __restrict__ x) {
    __shared__ __align__(16) float As[2][16][128];
    __shared__ __align__(16) float Bs[2][16][128];

    int rem = blockIdx.x, bi = 0, width = 16;
    while (rem >= width) { rem -= width; ++bi; --width; }
    int bj = bi + rem;

    const int tid = threadIdx.x;
    const int ty = tid >> 4, tx = tid & 15;
    ull acc2[8][4];
    const ull z = splat2(0.f);
    #pragma unroll
    for (int p = 0; p < 8; ++p)
        #pragma unroll
        for (int q = 0; q < 4; ++q) acc2[p][q] = z;

    const int r0 = tid >> 5, c40 = tid & 31;
    const int r1 = (tid + 256) >> 5, c41 = tid & 31;

    float4 pa0, pa1, pb0, pb1;
    {
        const float4* xr0 = (const float4*)(x + (size_t)r0 * Dn);
        const float4* xr1 = (const float4*)(x + (size_t)r1 * Dn);
        pa0 = xr0[bi * 32 + c40]; pb0 = xr0[bj * 32 + c40];
        pa1 = xr1[bi * 32 + c41]; pb1 = xr1[bj * 32 + c41];
        ((float4*)&As[0][r0][0])[c40] = pa0; ((float4*)&Bs[0][r0][0])[c40] = pb0;
        ((float4*)&As[0][r1][0])[c41] = pa1; ((float4*)&Bs[0][r1][0])[c41] = pb1;
    }

    int buf = 0;
    for (int n0 = 0; n0 < Nn; n0 += 16) {
        __syncthreads();
        const bool more = (n0 + 16 < Nn);
        if (more) {
            const float4* xr0 = (const float4*)(x + (size_t)(n0 + 16 + r0) * Dn);
            const float4* xr1 = (const float4*)(x + (size_t)(n0 + 16 + r1) * Dn);
            pa0 = xr0[bi * 32 + c40]; pb0 = xr0[bj * 32 + c40];
            pa1 = xr1[bi * 32 + c41]; pb1 = xr1[bj * 32 + c41];
        }
        #pragma unroll
        for (int kk = 0; kk < 16; ++kk) {
            float a8[8];
            *(float4*)&a8[0] = *(const float4*)&As[buf][kk][ty * 8];
            *(float4*)&a8[4] = *(const float4*)&As[buf][kk][ty * 8 + 4];
            const ull* bp = (const ull*)&Bs[buf][kk][tx * 8];
            ull b2[4];
            #pragma unroll
            for (int q = 0; q < 4; ++q) b2[q] = bp[q];
            #pragma unroll
            for (int p = 0; p < 8; ++p) {
                ull ap = splat2(a8[p]);
                #pragma unroll
                for (int q = 0; q < 4; ++q) fma2(acc2[p][q], ap, b2[q]);
            }
        }
        if (more) {
            int nb = buf ^ 1;
            ((float4*)&As[nb][r0][0])[c40] = pa0; ((float4*)&Bs[nb][r0][0])[c40] = pb0;
            ((float4*)&As[nb][r1][0])[c41] = pa1; ((float4*)&Bs[nb][r1][0])[c41] = pb1;
        }
        buf ^= 1;
    }

    int gi = bi * 128 + ty * 8;
    int gj = bj * 128 + tx * 8;
    float acc[8][8];
    #pragma unroll
    for (int p = 0; p < 8; ++p)
        #pragma unroll
        for (int q = 0; q < 4; ++q) {
            float2 v = *(float2*)&acc2[p][q];
            acc[p][2 * q] = v.x;
            acc[p][2 * q + 1] = v.y;
        }
    #pragma unroll
    for (int p = 0; p < 8; ++p) {
        float* dst = g_C + (size_t)(gi + p) * Dn + gj;
        *(float4*)(dst)     = make_float4(acc[p][0], acc[p][1], acc[p][2], acc[p][3]);
        *(float4*)(dst + 4) = make_float4(acc[p][4], acc[p][5], acc[p][6], acc[p][7]);
    }
    if (bi != bj) {
        #pragma unroll
        for (int q = 0; q < 8; ++q) {
            float* dst = g_C + (size_t)(gj + q) * Dn + gi;
            *(float4*)(dst)     = make_float4(acc[0][q], acc[1][q], acc[2][q], acc[3][q]);
            *(float4*)(dst + 4) = make_float4(acc[4][q], acc[5][q], acc[6][q], acc[7][q]);
        }
    }
}

// ---------------- persistent sequential CCIPCA solve ----------------
__global__ void __launch_bounds__(256) solve_kernel() {
    extern __shared__ __align__(16) float s_dyn[];
    float* s_C   = s_dyn;                                  // ROWS_PB*Dn
    float* s_WT  = s_dyn + ROWS_PB * Dn;                   // ROWS_PB*Kn
    float* s_VnT = s_dyn + ROWS_PB * Dn + ROWS_PB * Kn;    // ROWS_PB*Kn
    __shared__ __align__(16) float s_a[Dn];                // 8 KB
    __shared__ float sc3s[Kn], sc1[Kn], s_g[Kn];
    __shared__ float s_b[16], s_u[16], s_vk1[16];

    const int tid = threadIdx.x;
    const int bid = blockIdx.x;
    const int wid = tid >> 5, lane = tid & 31;
    int d_lo = bid * ROWS_PB; if (d_lo > Dn) d_lo = Dn;
    int d_hi = d_lo + ROWS_PB; if (d_hi > Dn) d_hi = Dn;
    const int nrows = d_hi - d_lo;
    unsigned gen = 0;

    // cache this block's C rows in SMEM (constant across all steps)
    {
        const float4* src = (const float4*)&g_C[(size_t)d_lo * Dn];
        float4* dst = (float4*)s_C;
        for (int i = tid; i < nrows * (Dn / 4); i += 256) dst[i] = src[i];
    }
    __syncthreads();

    for (int k = 0; k < Kn; ++k) {
        const int pin = k & 1, pout = pin ^ 1;

        // ---------------- P1 ----------------
        float s = 0.f, c1k1 = 0.f;
        if (k > 0) {
            s = rsqrtf(g_dn2[pin]);
            c1k1 = s * g_uv[pin];
            for (int j = tid; j < k - 1; j += 256) {
                sc3s[j] = g_c3[pin][j] * s;
                sc1[j]  = g_c1[pin][j];
            }
        }
        if (bid == NBLK - 1) {   // block 147 owns 0 rows: zeroing + barrier master
            for (int j = tid; j < Kn; j += 256) {
                g_c3[pout][j] = 0.f;
                g_c1[pout][j] = 0.f;
                g_g[j] = 0.f;
            }
            if (tid == 0) { g_dn2[pout] = 0.f; g_uv[pout] = 0.f; }
        }
        __syncthreads();

        if (k == 0) {
            for (int d = d_lo + tid; d < d_hi; d += 256)
                g_a[d] = g_Vt[d];
        } else {
            for (int dd = wid; dd < nrows; dd += 8) {
                int d = d_lo + dd;
                float u_d = s_u[dd];
                const float* wrow = &s_WT[dd * Kn];
                float sum1 = 0.f, sum2 = 0.f;
                #pragma unroll 4
                for (int j = lane; j < k - 1; j += 32) {
                    float wj = wrow[j];
                    sum1 += sc3s[j] * wj;
                    sum2 += sc1[j] * wj;
                }
                #pragma unroll
                for (int o = 16; o; o >>= 1) {
                    sum1 += __shfl_down_sync(~0u, sum1, o);
                    sum2 += __shfl_down_sync(~0u, sum2, o);
                }
                if (lane == 0) {
                    float vn_d = s * u_d;
                    float w_d = vn_d - sum1;
                    s_VnT[dd * Kn + (k - 1)] = vn_d;
                    g_VnT[(size_t)d * Kn + (k - 1)] = vn_d;  // for gemmOut
                    s_WT[dd * Kn + (k - 1)] = w_d;
                    g_a[d] = g_Vt[(size_t)k * Dn + d] - sum2 - c1k1 * w_d;
                }
            }
        }
        gbar(gen, bid);

        // ---------------- P2: b = C a (SMEM rows), g_j partials ----------------
        for (int i = tid; i < Dn / 4; i += 256)
            ((float4*)s_a)[i] = ((const float4*)g_a)[i];
        __syncthreads();
        for (int dd = wid; dd < nrows; dd += 8) {
            const float4* crow = (const float4*)&s_C[dd * Dn];
            float sum = 0.f;
            #pragma unroll 4
            for (int t = lane; t < Dn / 4; t += 32) {
                float4 c4 = crow[t];
                float4 a4 = ((const float4*)s_a)[t];
                sum += c4.x * a4.x + c4.y * a4.y + c4.z * a4.z + c4.w * a4.w;
            }
            #pragma unroll
            for (int o = 16; o; o >>= 1) sum += __shfl_down_sync(~0u, sum, o);
            if (lane == 0) s_b[dd] = sum;
        }
        __syncthreads();
        if (tid < k && nrows > 0) {
            float accg = 0.f;
            #pragma unroll 7
            for (int dd = 0; dd < nrows; ++dd)
                accg += s_WT[dd * Kn + tid] * s_b[dd];
            atomicAdd(&g_g[tid], accg);
        }
        gbar(gen, bid);

        // ---------------- P3: u update + next-step dots ----------------
        const float hh = 0.5f / g_d0[k];
        for (int j = tid; j < k; j += 256) s_g[j] = g_g[j];
        __syncthreads();
        for (int dd = wid; dd < nrows; dd += 8) {
            int d = d_lo + dd;
            const float* vrow = &s_VnT[dd * Kn];
            float sumg = 0.f;
            #pragma unroll 4
            for (int j = lane; j < k; j += 32) sumg += s_g[j] * vrow[j];
            #pragma unroll
            for (int o = 16; o; o >>= 1) sumg += __shfl_down_sync(~0u, sumg, o);
            if (lane == 0) {
                float u_d = 0.5f * g_Vt[(size_t)k * Dn + d] + hh * (s_b[dd] - sumg);
                s_u[dd] = u_d;
                s_vk1[dd] = (k + 1 < Kn) ? g_Vt[(size_t)(k + 1) * Dn + d] : 0.f;
            }
        }
        __syncthreads();
        if (tid < k && nrows > 0) {
            float a3 = 0.f, a1 = 0.f;
            #pragma unroll 7
            for (int dd = 0; dd < nrows; ++dd) {
                float vv = s_VnT[dd * Kn + tid];
                a3 += vv * s_u[dd];
                a1 += vv * s_vk1[dd];
            }
            atomicAdd(&g_c3[pout][tid], a3);
            atomicAdd(&g_c1[pout][tid], a1);
        }
        if (tid == 0 && nrows > 0) {
            float d2 = 0.f, uvv = 0.f;
            #pragma unroll 7
            for (int dd = 0; dd < nrows; ++dd) {
                d2  += s_u[dd] * s_u[dd];
                uvv += s_u[dd] * s_vk1[dd];
            }
            atomicAdd(&g_dn2[pout], d2);
            atomicAdd(&g_uv[pout], uvv);
        }
        gbar(gen, bid);
    }

    // epilogue: write vn_{K-1}
    {
        const int plast = ((Kn - 1) & 1) ^ 1;
        float sfin = rsqrtf(g_dn2[plast]);
        for (int dd = tid; dd < nrows; dd += 256)
            g_VnT[(size_t)(d_lo + dd) * Kn + (Kn - 1)] = sfin * s_u[dd];
    }

    // reset barrier state for the next graph replay (globally-last block)
    __syncthreads();
    if (tid == 0) {
        __threadfence();
        if (atomicAdd(&g_done, 1u) == (unsigned)(gridDim.x - 1)) {
            #pragma unroll
            for (int c = 0; c < 8; ++c) g_cnt[c * 256] = 0u;
            g_rel = 0u;
            g_done = 0u;
            __threadfence();
        }
    }
}

// ---------------- out = x @ VnT (double-buffered, f32x2) ----------------
__global__ void __launch_bounds__(256) gemmOut_kernel(const float* __restrict__ x,
                                                      float* __restrict__ out) {
    __shared__ __align__(16) float As[2][16][132];
    __shared__ __align__(16) float Bs[2][16][64];

    const int br = blockIdx.x >> 2;
    const int bc = blockIdx.x & 3;
    const int tid = threadIdx.x;
    const int ty = tid >> 4, tx = tid & 15;
    const int n0 = br * 128;

    ull acc2[8][2];
    const ull z = splat2(0.f);
    #pragma unroll
    for (int p = 0; p < 8; ++p) { acc2[p][0] = z; acc2[p][1] = z; }

    const int ra0 = tid >> 2, ca0 = tid & 3;
    const int ra1 = (tid + 256) >> 2, ca1 = tid & 3;
    const int rb = tid >> 4, cb = tid & 15;

    float4 va0, va1, vb;
    auto stage = [&](int b) {
        As[b][ca0 * 4 + 0][ra0] = va0.x;
        As[b][ca0 * 4 + 1][ra0] = va0.y;
        As[b][ca0 * 4 + 2][ra0] = va0.z;
        As[b][ca0 * 4 + 3][ra0] = va0.w;
        As[b][ca1 * 4 + 0][ra1] = va1.x;
        As[b][ca1 * 4 + 1][ra1] = va1.y;
        As[b][ca1 * 4 + 2][ra1] = va1.z;
        As[b][ca1 * 4 + 3][ra1] = va1.w;
        ((float4*)&Bs[b][rb][0])[cb] = vb;
    };

    va0 = *(const float4*)(x + (size_t)(n0 + ra0) * Dn + ca0 * 4);
    va1 = *(const float4*)(x + (size_t)(n0 + ra1) * Dn + ca1 * 4);
    vb  = *(const float4*)(&g_VnT[(size_t)rb * Kn + bc * 64 + cb * 4]);
    stage(0);

    int buf = 0;
    for (int dchunk = 0; dchunk < Dn; dchunk += 16) {
        __syncthreads();
        const bool more = (dchunk + 16 < Dn);
        if (more) {
            int dn = dchunk + 16;
            va0 = *(const float4*)(x + (size_t)(n0 + ra0) * Dn + dn + ca0 * 4);
            va1 = *(const float4*)(x + (size_t)(n0 + ra1) * Dn + dn + ca1 * 4);
            vb  = *(const float4*)(&g_VnT[(size_t)(dn + rb) * Kn + bc * 64 + cb * 4]);
        }
        #pragma unroll
        for (int kk = 0; kk < 16; ++kk) {
            float a8[8];
            *(float4*)&a8[0] = *(const float4*)&As[buf][kk][ty * 8];
            *(float4*)&a8[4] = *(const float4*)&As[buf][kk][ty * 8 + 4];
            const ull* bp = (const ull*)&Bs[buf][kk][tx * 4];
            ull b2[2] = { bp[0], bp[1] };
            #pragma unroll
            for (int p = 0; p < 8; ++p) {
                ull ap = splat2(a8[p]);
                fma2(acc2[p][0], ap, b2[0]);
                fma2(acc2[p][1], ap, b2[1]);
            }
        }
        if (more) stage(buf ^ 1);
        buf ^= 1;
    }

    #pragma unroll
    for (int p = 0; p < 8; ++p) {
        float2 v0 = *(float2*)&acc2[p][0];
        float2 v1 = *(float2*)&acc2[p][1];
        *(float4*)(out + (size_t)(n0 + ty * 8 + p) * Kn + bc * 64 + tx * 4) =
            make_float4(v0.x, v0.y, v1.x, v1.y);
    }
}

// ---------------- launch ----------------
extern "C" void kernel_launch(void* const* d_in, const int* in_sizes, int n_in,
                              void* d_out, int out_size) {
    const float* x  = (const float*)d_in[0];
    const float* V0 = (const float*)d_in[1];
    if (n_in >= 2 && in_sizes[0] == Dn * Kn && in_sizes[1] == Nn * Dn) {
        const float* t = x; x = V0; V0 = t;
    }
    float* out = (float*)d_out;

    static int smem_set = 0;
    const int dyn_smem = (ROWS_PB * Dn + 2 * ROWS_PB * Kn) * (int)sizeof(float); // 143360
    if (!smem_set) {
        cudaFuncSetAttribute(solve_kernel,
                             cudaFuncAttributeMaxDynamicSharedMemorySize, dyn_smem);
        smem_set = 1;
    }

    prep_kernel<<<Kn, 256>>>(V0);
    gemmC_kernel<<<136, 256>>>(x);
    solve_kernel<<<NBLK, 256, dyn_smem>>>();
    gemmOut_kernel<<<256, 256>>>(x, out);
}

// round 9
// speedup vs baseline: 1.5523x; 1.5523x over previous
#include <cuda_runtime.h>
#include <math.h>

#define Nn 8192
#define Dn 2048
#define Kn 256
#define NBLK 148
#define ROWS_PB 14            // 146*14=2044, block146->4 rows, block147->0 rows

typedef unsigned long long ull;

// ---------------- f32x2 packed FMA helpers (Blackwell FFMA2) ----------------
__device__ __forceinline__ ull splat2(float s) {
    ull d;
    asm("mov.b64 %0, {%1, %1};" : "=l"(d) : "r"(__float_as_uint(s)));
    return d;
}
__device__ __forceinline__ void fma2(ull& d, ull a, ull b) {
    asm("fma.rn.f32x2 %0, %1, %2, %0;" : "+l"(d) : "l"(a), "l"(b));
}

// ---------------- device scratch (static: no allocation allowed) ----------------
__device__ float g_C[(size_t)Dn * Dn];       // 16 MB  C = x^T x
__device__ float g_Vt[(size_t)Kn * Dn];      // Vt[k][d] = V0[d][k]
__device__ float g_VnT[(size_t)Dn * Kn];     // VnT[d][j] = vn_j[d] (for gemmOut)
__device__ float g_a[Dn];
// 8-way sharded accumulators: shard = bid & 7. Shards are Kn floats (1KB)
// apart -> distinct L2 lines/slices -> ~19 atomic ops per address instead of 148.
__device__ float g_c1[2][8][Kn];             // vn_j . v_k   partial shards
__device__ float g_c3[2][8][Kn];             // vn_j . u     partial shards
__device__ float g_g[8][Kn];                 // w_j . b      partial shards
__device__ float g_dn2s[2][8 * 32];          // |u|^2 shards (128B apart)
__device__ float g_uvs[2][8 * 32];           // u.v_{k+1} shards
__device__ float g_d0[Kn];
__device__ __align__(128) unsigned g_barcnt; // monotonic barrier counter
__device__ __align__(128) unsigned g_done;

// ---------------- grid barrier (R3 design — measured fastest; keep) -----------
__device__ __forceinline__ void gbar(unsigned& gen) {
    gen += gridDim.x;
    __syncthreads();
    if (threadIdx.x == 0) {
        asm volatile("red.release.gpu.global.add.u32 [%0], 1;"
                     :: "l"(&g_barcnt) : "memory");
        unsigned v;
        do {
            asm volatile("ld.acquire.gpu.global.u32 %0, [%1];"
                         : "=r"(v) : "l"(&g_barcnt) : "memory");
        } while ((int)(v - gen) < 0);
    }
    __syncthreads();
}

// ---------------- prep: transpose V0 -> Vt, per-column norms d0 ----------------
__global__ void __launch_bounds__(256) prep_kernel(const float* __restrict__ V0) {
    __shared__ float sb[8];
    int k = blockIdx.x;
    float s = 0.f;
    for (int d = threadIdx.x; d < Dn; d += 256) {
        float v = V0[(size_t)d * Kn + k];
        g_Vt[(size_t)k * Dn + d] = v;
        s += v * v;
    }
    #pragma unroll
    for (int o = 16; o; o >>= 1) s += __shfl_down_sync(~0u, s, o);
    if ((threadIdx.x & 31) == 0) sb[threadIdx.x >> 5] = s;
    __syncthreads();
    if (threadIdx.x == 0) {
        float t = 0.f;
        #pragma unroll
        for (int w = 0; w < 8; ++w) t += sb[w];
        g_d0[k] = sqrtf(t);
    }
}

// ---------------- C = x^T x (symmetric, double-buffered, f32x2) ----------------
__global__ void __launch_bounds__(256) gemmC_kernel(const float* __restrict__ x) {
    __shared__ __align__(16) float As[2][16][128];
    __shared__ __align__(16) float Bs[2][16][128];

    int rem = blockIdx.x, bi = 0, width = 16;
    while (rem >= width) { rem -= width; ++bi; --width; }
    int bj = bi + rem;

    const int tid = threadIdx.x;
    const int ty = tid >> 4, tx = tid & 15;
    ull acc2[8][4];
    const ull z = splat2(0.f);
    #pragma unroll
    for (int p = 0; p < 8; ++p)
        #pragma unroll
        for (int q = 0; q < 4; ++q) acc2[p][q] = z;

    const int r0 = tid >> 5, c40 = tid & 31;
    const int r1 = (tid + 256) >> 5, c41 = tid & 31;

    float4 pa0, pa1, pb0, pb1;
    {
        const float4* xr0 = (const float4*)(x + (size_t)r0 * Dn);
        const float4* xr1 = (const float4*)(x + (size_t)r1 * Dn);
        pa0 = xr0[bi * 32 + c40]; pb0 = xr0[bj * 32 + c40];
        pa1 = xr1[bi * 32 + c41]; pb1 = xr1[bj * 32 + c41];
        ((float4*)&As[0][r0][0])[c40] = pa0; ((float4*)&Bs[0][r0][0])[c40] = pb0;
        ((float4*)&As[0][r1][0])[c41] = pa1; ((float4*)&Bs[0][r1][0])[c41] = pb1;
    }

    int buf = 0;
    for (int n0 = 0; n0 < Nn; n0 += 16) {
        __syncthreads();
        const bool more = (n0 + 16 < Nn);
        if (more) {
            const float4* xr0 = (const float4*)(x + (size_t)(n0 + 16 + r0) * Dn);
            const float4* xr1 = (const float4*)(x + (size_t)(n0 + 16 + r1) * Dn);
            pa0 = xr0[bi * 32 + c40]; pb0 = xr0[bj * 32 + c40];
            pa1 = xr1[bi * 32 + c41]; pb1 = xr1[bj * 32 + c41];
        }
        #pragma unroll
        for (int kk = 0; kk < 16; ++kk) {
            float a8[8];
            *(float4*)&a8[0] = *(const float4*)&As[buf][kk][ty * 8];
            *(float4*)&a8[4] = *(const float4*)&As[buf][kk][ty * 8 + 4];
            const ull* bp = (const ull*)&Bs[buf][kk][tx * 8];
            ull b2[4];
            #pragma unroll
            for (int q = 0; q < 4; ++q) b2[q] = bp[q];
            #pragma unroll
            for (int p = 0; p < 8; ++p) {
                ull ap = splat2(a8[p]);
                #pragma unroll
                for (int q = 0; q < 4; ++q) fma2(acc2[p][q], ap, b2[q]);
            }
        }
        if (more) {
            int nb = buf ^ 1;
            ((float4*)&As[nb][r0][0])[c40] = pa0; ((float4*)&Bs[nb][r0][0])[c40] = pb0;
            ((float4*)&As[nb][r1][0])[c41] = pa1; ((float4*)&Bs[nb][r1][0])[c41] = pb1;
        }
        buf ^= 1;
    }

    int gi = bi * 128 + ty * 8;
    int gj = bj * 128 + tx * 8;
    float acc[8][8];
    #pragma unroll
    for (int p = 0; p < 8; ++p)
        #pragma unroll
        for (int q = 0; q < 4; ++q) {
            float2 v = *(float2*)&acc2[p][q];
            acc[p][2 * q] = v.x;
            acc[p][2 * q + 1] = v.y;
        }
    #pragma unroll
    for (int p = 0; p < 8; ++p) {
        float* dst = g_C + (size_t)(gi + p) * Dn + gj;
        *(float4*)(dst)     = make_float4(acc[p][0], acc[p][1], acc[p][2], acc[p][3]);
        *(float4*)(dst + 4) = make_float4(acc[p][4], acc[p][5], acc[p][6], acc[p][7]);
    }
    if (bi != bj) {
        #pragma unroll
        for (int q = 0; q < 8; ++q) {
            float* dst = g_C + (size_t)(gj + q) * Dn + gi;
            *(float4*)(dst)     = make_float4(acc[0][q], acc[1][q], acc[2][q], acc[3][q]);
            *(float4*)(dst + 4) = make_float4(acc[4][q], acc[5][q], acc[6][q], acc[7][q]);
        }
    }
}

// ---------------- persistent sequential CCIPCA solve ----------------
__global__ void __launch_bounds__(256) solve_kernel() {
    extern __shared__ __align__(16) float s_dyn[];
    float* s_C   = s_dyn;                                  // ROWS_PB*Dn
    float* s_WT  = s_dyn + ROWS_PB * Dn;                   // ROWS_PB*Kn
    float* s_VnT = s_dyn + ROWS_PB * Dn + ROWS_PB * Kn;    // ROWS_PB*Kn
    __shared__ __align__(16) float s_a[Dn];                // 8 KB
    __shared__ float sc3s[Kn], sc1[Kn], s_g[Kn];
    __shared__ float s_b[16], s_u[16], s_vk1[16];

    const int tid = threadIdx.x;
    const int bid = blockIdx.x;
    const int shard = bid & 7;
    const int wid = tid >> 5, lane = tid & 31;
    int d_lo = bid * ROWS_PB; if (d_lo > Dn) d_lo = Dn;
    int d_hi = d_lo + ROWS_PB; if (d_hi > Dn) d_hi = Dn;
    const int nrows = d_hi - d_lo;
    unsigned gen = 0;

    // cache this block's C rows in SMEM (constant across all steps)
    {
        const float4* src = (const float4*)&g_C[(size_t)d_lo * Dn];
        float4* dst = (float4*)s_C;
        for (int i = tid; i < nrows * (Dn / 4); i += 256) dst[i] = src[i];
    }
    __syncthreads();

    for (int k = 0; k < Kn; ++k) {
        const int pin = k & 1, pout = pin ^ 1;

        // ---------------- P1 ----------------
        float s = 0.f, c1k1 = 0.f;
        if (k > 0) {
            float dn2 = 0.f, uv = 0.f;
            #pragma unroll
            for (int ss = 0; ss < 8; ++ss) {
                dn2 += g_dn2s[pin][ss * 32];
                uv  += g_uvs[pin][ss * 32];
            }
            s = rsqrtf(dn2);
            c1k1 = s * uv;
            for (int j = tid; j < k - 1; j += 256) {
                float t3 = 0.f, t1 = 0.f;
                #pragma unroll
                for (int ss = 0; ss < 8; ++ss) {
                    t3 += g_c3[pin][ss][j];
                    t1 += g_c1[pin][ss][j];
                }
                sc3s[j] = t3 * s;
                sc1[j]  = t1;
            }
        }
        if (bid == NBLK - 1) {   // block 147 owns 0 rows: zero next-step shards
            float* z3 = &g_c3[pout][0][0];
            float* z1 = &g_c1[pout][0][0];
            float* zg = &g_g[0][0];
            for (int j = tid; j < 8 * Kn; j += 256) {
                z3[j] = 0.f; z1[j] = 0.f; zg[j] = 0.f;
            }
            if (tid < 8) {
                g_dn2s[pout][tid * 32] = 0.f;
                g_uvs[pout][tid * 32] = 0.f;
            }
        }
        __syncthreads();

        if (k == 0) {
            for (int d = d_lo + tid; d < d_hi; d += 256)
                g_a[d] = g_Vt[d];
        } else {
            for (int dd = wid; dd < nrows; dd += 8) {
                int d = d_lo + dd;
                float u_d = s_u[dd];
                const float* wrow = &s_WT[dd * Kn];
                float sum1 = 0.f, sum2 = 0.f;
                #pragma unroll 4
                for (int j = lane; j < k - 1; j += 32) {
                    float wj = wrow[j];
                    sum1 += sc3s[j] * wj;
                    sum2 += sc1[j] * wj;
                }
                #pragma unroll
                for (int o = 16; o; o >>= 1) {
                    sum1 += __shfl_down_sync(~0u, sum1, o);
                    sum2 += __shfl_down_sync(~0u, sum2, o);
                }
                if (lane == 0) {
                    float vn_d = s * u_d;
                    float w_d = vn_d - sum1;
                    s_VnT[dd * Kn + (k - 1)] = vn_d;
                    g_VnT[(size_t)d * Kn + (k - 1)] = vn_d;  // for gemmOut
                    s_WT[dd * Kn + (k - 1)] = w_d;
                    g_a[d] = g_Vt[(size_t)k * Dn + d] - sum2 - c1k1 * w_d;
                }
            }
        }
        gbar(gen);

        // ---------------- P2: b = C a (SMEM rows), sharded g_j partials -------
        for (int i = tid; i < Dn / 4; i += 256)
            ((float4*)s_a)[i] = ((const float4*)g_a)[i];
        __syncthreads();
        for (int dd = wid; dd < nrows; dd += 8) {
            const float4* crow = (const float4*)&s_C[dd * Dn];
            float sum = 0.f;
            #pragma unroll 4
            for (int t = lane; t < Dn / 4; t += 32) {
                float4 c4 = crow[t];
                float4 a4 = ((const float4*)s_a)[t];
                sum += c4.x * a4.x + c4.y * a4.y + c4.z * a4.z + c4.w * a4.w;
            }
            #pragma unroll
            for (int o = 16; o; o >>= 1) sum += __shfl_down_sync(~0u, sum, o);
            if (lane == 0) s_b[dd] = sum;
        }
        __syncthreads();
        if (tid < k && nrows > 0) {
            float accg = 0.f;
            #pragma unroll 7
            for (int dd = 0; dd < nrows; ++dd)
                accg += s_WT[dd * Kn + tid] * s_b[dd];
            atomicAdd(&g_g[shard][tid], accg);
        }
        gbar(gen);

        // ---------------- P3: u update + next-step dots ----------------
        const float hh = 0.5f / g_d0[k];
        for (int j = tid; j < k; j += 256) {
            float tg = 0.f;
            #pragma unroll
            for (int ss = 0; ss < 8; ++ss) tg += g_g[ss][j];
            s_g[j] = tg;
        }
        __syncthreads();
        for (int dd = wid; dd < nrows; dd += 8) {
            int d = d_lo + dd;
            const float* vrow = &s_VnT[dd * Kn];
            float sumg = 0.f;
            #pragma unroll 4
            for (int j = lane; j < k; j += 32) sumg += s_g[j] * vrow[j];
            #pragma unroll
            for (int o = 16; o; o >>= 1) sumg += __shfl_down_sync(~0u, sumg, o);
            if (lane == 0) {
                float u_d = 0.5f * g_Vt[(size_t)k * Dn + d] + hh * (s_b[dd] - sumg);
                s_u[dd] = u_d;
                s_vk1[dd] = (k + 1 < Kn) ? g_Vt[(size_t)(k + 1) * Dn + d] : 0.f;
            }
        }
        __syncthreads();
        if (tid < k && nrows > 0) {
            float a3 = 0.f, a1 = 0.f;
            #pragma unroll 7
            for (int dd = 0; dd < nrows; ++dd) {
                float vv = s_VnT[dd * Kn + tid];
                a3 += vv * s_u[dd];
                a1 += vv * s_vk1[dd];
            }
            atomicAdd(&g_c3[pout][shard][tid], a3);
            atomicAdd(&g_c1[pout][shard][tid], a1);
        }
        if (tid == 0 && nrows > 0) {
            float d2 = 0.f, uvv = 0.f;
            #pragma unroll 7
            for (int dd = 0; dd < nrows; ++dd) {
                d2  += s_u[dd] * s_u[dd];
                uvv += s_u[dd] * s_vk1[dd];
            }
            atomicAdd(&g_dn2s[pout][shard * 32], d2);
            atomicAdd(&g_uvs[pout][shard * 32], uvv);
        }
        gbar(gen);
    }

    // epilogue: write vn_{K-1}
    {
        const int plast = ((Kn - 1) & 1) ^ 1;
        float dn2 = 0.f;
        #pragma unroll
        for (int ss = 0; ss < 8; ++ss) dn2 += g_dn2s[plast][ss * 32];
        float sfin = rsqrtf(dn2);
        for (int dd = tid; dd < nrows; dd += 256)
            g_VnT[(size_t)(d_lo + dd) * Kn + (Kn - 1)] = sfin * s_u[dd];
    }

    // reset barrier state for the next graph replay (globally-last block)
    __syncthreads();
    if (tid == 0) {
        __threadfence();
        if (atomicAdd(&g_done, 1u) == (unsigned)(gridDim.x - 1)) {
            g_done = 0u;
            g_barcnt = 0u;
            __threadfence();
        }
    }
}

// ---------------- out = x @ VnT (double-buffered, f32x2) ----------------
__global__ void __launch_bounds__(256) gemmOut_kernel(const float* __restrict__ x,
                                                      float* __restrict__ out) {
    __shared__ __align__(16) float As[2][16][132];
    __shared__ __align__(16) float Bs[2][16][64];

    const int br = blockIdx.x >> 2;
    const int bc = blockIdx.x & 3;
    const int tid = threadIdx.x;
    const int ty = tid >> 4, tx = tid & 15;
    const int n0 = br * 128;

    ull acc2[8][2];
    const ull z = splat2(0.f);
    #pragma unroll
    for (int p = 0; p < 8; ++p) { acc2[p][0] = z; acc2[p][1] = z; }

    const int ra0 = tid >> 2, ca0 = tid & 3;
    const int ra1 = (tid + 256) >> 2, ca1 = tid & 3;
    const int rb = tid >> 4, cb = tid & 15;

    float4 va0, va1, vb;
    auto stage = [&](int b) {
        As[b][ca0 * 4 + 0][ra0] = va0.x;
        As[b][ca0 * 4 + 1][ra0] = va0.y;
        As[b][ca0 * 4 + 2][ra0] = va0.z;
        As[b][ca0 * 4 + 3][ra0] = va0.w;
        As[b][ca1 * 4 + 0][ra1] = va1.x;
        As[b][ca1 * 4 + 1][ra1] = va1.y;
        As[b][ca1 * 4 + 2][ra1] = va1.z;
        As[b][ca1 * 4 + 3][ra1] = va1.w;
        ((float4*)&Bs[b][rb][0])[cb] = vb;
    };

    va0 = *(const float4*)(x + (size_t)(n0 + ra0) * Dn + ca0 * 4);
    va1 = *(const float4*)(x + (size_t)(n0 + ra1) * Dn + ca1 * 4);
    vb  = *(const float4*)(&g_VnT[(size_t)rb * Kn + bc * 64 + cb * 4]);
    stage(0);

    int buf = 0;
    for (int dchunk = 0; dchunk < Dn; dchunk += 16) {
        __syncthreads();
        const bool more = (dchunk + 16 < Dn);
        if (more) {
            int dn = dchunk + 16;
            va0 = *(const float4*)(x + (size_t)(n0 + ra0) * Dn + dn + ca0 * 4);
            va1 = *(const float4*)(x + (size_t)(n0 + ra1) * Dn + dn + ca1 * 4);
            vb  = *(const float4*)(&g_VnT[(size_t)(dn + rb) * Kn + bc * 64 + cb * 4]);
        }
        #pragma unroll
        for (int kk = 0; kk < 16; ++kk) {
            float a8[8];
            *(float4*)&a8[0] = *(const float4*)&As[buf][kk][ty * 8];
            *(float4*)&a8[4] = *(const float4*)&As[buf][kk][ty * 8 + 4];
            const ull* bp = (const ull*)&Bs[buf][kk][tx * 4];
            ull b2[2] = { bp[0], bp[1] };
            #pragma unroll
            for (int p = 0; p < 8; ++p) {
                ull ap = splat2(a8[p]);
                fma2(acc2[p][0], ap, b2[0]);
                fma2(acc2[p][1], ap, b2[1]);
            }
        }
        if (more) stage(buf ^ 1);
        buf ^= 1;
    }

    #pragma unroll
    for (int p = 0; p < 8; ++p) {
        float2 v0 = *(float2*)&acc2[p][0];
        float2 v1 = *(float2*)&acc2[p][1];
        *(float4*)(out + (size_t)(n0 + ty * 8 + p) * Kn + bc * 64 + tx * 4) =
            make_float4(v0.x, v0.y, v1.x, v1.y);
    }
}

// ---------------- launch ----------------
extern "C" void kernel_launch(void* const* d_in, const int* in_sizes, int n_in,
                              void* d_out, int out_size) {
    const float* x  = (const float*)d_in[0];
    const float* V0 = (const float*)d_in[1];
    if (n_in >= 2 && in_sizes[0] == Dn * Kn && in_sizes[1] == Nn * Dn) {
        const float* t = x; x = V0; V0 = t;
    }
    float* out = (float*)d_out;

    static int smem_set = 0;
    const int dyn_smem = (ROWS_PB * Dn + 2 * ROWS_PB * Kn) * (int)sizeof(float); // 143360
    if (!smem_set) {
        cudaFuncSetAttribute(solve_kernel,
                             cudaFuncAttributeMaxDynamicSharedMemorySize, dyn_smem);
        smem_set = 1;
    }

    prep_kernel<<<Kn, 256>>>(V0);
    gemmC_kernel<<<136, 256>>>(x);
    solve_kernel<<<NBLK, 256, dyn_smem>>>();
    gemmOut_kernel<<<256, 256>>>(x, out);
}

// round 10
// speedup vs baseline: 1.9320x; 1.2446x over previous
#include <cuda_runtime.h>
#include <cuda_bf16.h>
#include <math.h>

#define Nn 8192
#define Dn 2048
#define Kn 256
#define NBLK 148
#define ROWS_PB 14            // 148 * 14 = 2072 >= 2048

typedef unsigned long long ull;
typedef unsigned int u32;

// ---------------- f32x2 packed FMA helpers (Blackwell FFMA2) ----------------
__device__ __forceinline__ ull splat2(float s) {
    ull d;
    asm("mov.b64 %0, {%1, %1};" : "=l"(d) : "r"(__float_as_uint(s)));
    return d;
}
__device__ __forceinline__ void fma2(ull& d, ull a, ull b) {
    asm("fma.rn.f32x2 %0, %1, %2, %0;" : "+l"(d) : "l"(a), "l"(b));
}

// ---------------- device scratch (static: no allocation allowed) ----------------
__device__ float g_C[(size_t)Dn * Dn];       // 16 MB  C = x^T x
__device__ __nv_bfloat16 g_xh[(size_t)Nn * Dn];  // 32 MB hi split
__device__ __nv_bfloat16 g_xl[(size_t)Nn * Dn];  // 32 MB lo split
__device__ float g_Vt[(size_t)Kn * Dn];      // Vt[k][d] = V0[d][k]
__device__ float g_VnT[(size_t)Dn * Kn];     // VnT[d][j] = vn_j[d]
__device__ float g_a[Dn];
__device__ float g_c1[2][Kn];
__device__ float g_c3[2][Kn];
__device__ float g_g[Kn];
__device__ float g_d0[Kn];
__device__ float g_dn2[2];
__device__ float g_uv[2];
__device__ __align__(128) unsigned g_barcnt;
__device__ __align__(128) unsigned g_done;

// ---------------- grid barrier (R3 design — measured fastest) -----------------
__device__ __forceinline__ void gbar(unsigned& gen) {
    gen += gridDim.x;
    __syncthreads();
    if (threadIdx.x == 0) {
        asm volatile("red.release.gpu.global.add.u32 [%0], 1;"
                     :: "l"(&g_barcnt) : "memory");
        unsigned v;
        do {
            asm volatile("ld.acquire.gpu.global.u32 %0, [%1];"
                         : "=r"(v) : "l"(&g_barcnt) : "memory");
        } while ((int)(v - gen) < 0);
    }
    __syncthreads();
}

// ---------------- split x into bf16 hi + lo ----------------
__global__ void __launch_bounds__(256) splitx_kernel(const float* __restrict__ x) {
    const int stride = gridDim.x * 256;
    for (int i = blockIdx.x * 256 + threadIdx.x; i < Nn * Dn / 4; i += stride) {
        float4 v = ((const float4*)x)[i];
        __nv_bfloat16 h0 = __float2bfloat16(v.x);
        __nv_bfloat16 h1 = __float2bfloat16(v.y);
        __nv_bfloat16 h2 = __float2bfloat16(v.z);
        __nv_bfloat16 h3 = __float2bfloat16(v.w);
        __nv_bfloat16 l0 = __float2bfloat16(v.x - __bfloat162float(h0));
        __nv_bfloat16 l1 = __float2bfloat16(v.y - __bfloat162float(h1));
        __nv_bfloat16 l2 = __float2bfloat16(v.z - __bfloat162float(h2));
        __nv_bfloat16 l3 = __float2bfloat16(v.w - __bfloat162float(h3));
        ushort4 hh, ll;
        hh.x = *(unsigned short*)&h0; hh.y = *(unsigned short*)&h1;
        hh.z = *(unsigned short*)&h2; hh.w = *(unsigned short*)&h3;
        ll.x = *(unsigned short*)&l0; ll.y = *(unsigned short*)&l1;
        ll.z = *(unsigned short*)&l2; ll.w = *(unsigned short*)&l3;
        ((ushort4*)g_xh)[i] = hh;
        ((ushort4*)g_xl)[i] = ll;
    }
}

// ---------------- prep: transpose V0 -> Vt, per-column norms d0 ----------------
__global__ void __launch_bounds__(256) prep_kernel(const float* __restrict__ V0) {
    __shared__ float sb[8];
    int k = blockIdx.x;
    float s = 0.f;
    for (int d = threadIdx.x; d < Dn; d += 256) {
        float v = V0[(size_t)d * Kn + k];
        g_Vt[(size_t)k * Dn + d] = v;
        s += v * v;
    }
    #pragma unroll
    for (int o = 16; o; o >>= 1) s += __shfl_down_sync(~0u, s, o);
    if ((threadIdx.x & 31) == 0) sb[threadIdx.x >> 5] = s;
    __syncthreads();
    if (threadIdx.x == 0) {
        float t = 0.f;
        #pragma unroll
        for (int w = 0; w < 8; ++w) t += sb[w];
        g_d0[k] = sqrtf(t);
    }
}

// ---------------- tensor-core helpers ----------------
__device__ __forceinline__ void ldsm4t(u32& r0, u32& r1, u32& r2, u32& r3, u32 addr) {
    asm volatile("ldmatrix.sync.aligned.m8n8.x4.trans.shared.b16 {%0,%1,%2,%3}, [%4];"
                 : "=r"(r0), "=r"(r1), "=r"(r2), "=r"(r3) : "r"(addr));
}
__device__ __forceinline__ void mma16816(float* c, const u32* a, const u32* b) {
    asm volatile(
        "mma.sync.aligned.m16n8k16.row.col.f32.bf16.bf16.f32 "
        "{%0,%1,%2,%3}, {%4,%5,%6,%7}, {%8,%9}, {%0,%1,%2,%3};"
        : "+f"(c[0]), "+f"(c[1]), "+f"(c[2]), "+f"(c[3])
        : "r"(a[0]), "r"(a[1]), "r"(a[2]), "r"(a[3]), "r"(b[0]), "r"(b[1]));
}

// ---------------- C = xh^T xh + xh^T xl + xl^T xh (tensor cores) ---------------
// 136 blocks, symmetric 128x128 tile pairs. Tiles staged in swizzled smem,
// fragments via ldmatrix.x4.trans, fp32 accumulators.
__global__ void __launch_bounds__(256) gemmC_tc_kernel() {
    // smem: [buf][tile(Ah,Al,Bh,Bl)][16 rows x 256B]  = 32 KB
    __shared__ __align__(16) char smt[2][4][16 * 256];

    int rem = blockIdx.x, bi = 0, width = 16;
    while (rem >= width) { rem -= width; ++bi; --width; }
    int bj = bi + rem;

    const int tid = threadIdx.x;
    const int warp = tid >> 5, lane = tid & 31;
    const int wm = warp >> 2, wn = warp & 3;    // warp tile 64(m) x 32(n)

    float acc[4][4][4];
    #pragma unroll
    for (int i = 0; i < 4; ++i)
        #pragma unroll
        for (int j = 0; j < 4; ++j)
            #pragma unroll
            for (int r = 0; r < 4; ++r) acc[i][j][r] = 0.f;

    // ---- global load mapping: each thread loads 4 x 16B chunks (one per tile)
    const int ln = tid >> 4;         // row 0..15
    const int lc = tid & 15;         // 16B chunk 0..15
    const int sw_off = ln * 256 + ((lc ^ (ln & 7)) << 4);   // swizzled smem offset
    // global source (halfs): row (n0+ln)*Dn + colbase + lc*8
    const size_t gA = (size_t)ln * Dn + bi * 128 + lc * 8;
    const size_t gB = (size_t)ln * Dn + bj * 128 + lc * 8;

    // ---- precompute ldmatrix lane addresses (offsets within a tile) ----
    const int q = lane >> 3, r8 = lane & 7;
    // A frag (m16 x k16) quads: (m0k0),(m8k0),(m0k8),(m8k8)
    int a_colh[4], a_row[4];
    #pragma unroll
    for (int i = 0; i < 4; ++i) {
        int m_off = (q & 1) << 3, k_off = (q >> 1) << 3;
        a_colh[i] = wm * 64 + (i << 4) + m_off;
        a_row[i]  = k_off + r8;
    }
    // B frag pairs p=0,1 (n offsets 16p / 16p+8) quads: (n0k0),(n0k8),(n8k0),(n8k8)
    int b_colh[2], b_row[2];
    #pragma unroll
    for (int p = 0; p < 2; ++p) {
        int n_off = (p << 4) + ((q >> 1) << 3);
        int k_off = (q & 1) << 3;
        b_colh[p] = wn * 32 + n_off;
        b_row[p]  = k_off + r8;
    }
    u32 aoff[4], boff[2];
    #pragma unroll
    for (int i = 0; i < 4; ++i)
        aoff[i] = a_row[i] * 256 + ((((u32)a_colh[i] >> 3) ^ (a_row[i] & 7)) << 4);
    #pragma unroll
    for (int p = 0; p < 2; ++p)
        boff[p] = b_row[p] * 256 + ((((u32)b_colh[p] >> 3) ^ (b_row[p] & 7)) << 4);

    const u32 smem_base = (u32)__cvta_generic_to_shared(&smt[0][0][0]);

    // ---- prime buffer 0 ----
    uint4 pf0, pf1, pf2, pf3;
    pf0 = *(const uint4*)(g_xh + gA);
    pf1 = *(const uint4*)(g_xl + gA);
    pf2 = *(const uint4*)(g_xh + gB);
    pf3 = *(const uint4*)(g_xl + gB);
    *(uint4*)(smt[0][0] + sw_off) = pf0;
    *(uint4*)(smt[0][1] + sw_off) = pf1;
    *(uint4*)(smt[0][2] + sw_off) = pf2;
    *(uint4*)(smt[0][3] + sw_off) = pf3;
    __syncthreads();

    int buf = 0;
    for (int n0 = 0; n0 < Nn; n0 += 16) {
        const bool more = (n0 + 16 < Nn);
        if (more) {
            size_t adv = (size_t)(n0 + 16) * Dn;
            pf0 = *(const uint4*)(g_xh + gA + adv);
            pf1 = *(const uint4*)(g_xl + gA + adv);
            pf2 = *(const uint4*)(g_xh + gB + adv);
            pf3 = *(const uint4*)(g_xl + gB + adv);
        }
        const u32 tb = smem_base + buf * (4 * 4096);
        u32 Ah[4][4], Al[4][4], Bh[4][2], Bl[4][2];
        #pragma unroll
        for (int i = 0; i < 4; ++i) {
            ldsm4t(Ah[i][0], Ah[i][1], Ah[i][2], Ah[i][3], tb + 0 * 4096 + aoff[i]);
            ldsm4t(Al[i][0], Al[i][1], Al[i][2], Al[i][3], tb + 1 * 4096 + aoff[i]);
        }
        #pragma unroll
        for (int p = 0; p < 2; ++p) {
            ldsm4t(Bh[2 * p][0], Bh[2 * p][1], Bh[2 * p + 1][0], Bh[2 * p + 1][1],
                   tb + 2 * 4096 + boff[p]);
            ldsm4t(Bl[2 * p][0], Bl[2 * p][1], Bl[2 * p + 1][0], Bl[2 * p + 1][1],
                   tb + 3 * 4096 + boff[p]);
        }
        #pragma unroll
        for (int i = 0; i < 4; ++i)
            #pragma unroll
            for (int j = 0; j < 4; ++j) {
                mma16816(acc[i][j], Ah[i], Bh[j]);
                mma16816(acc[i][j], Ah[i], Bl[j]);
                mma16816(acc[i][j], Al[i], Bh[j]);
            }
        if (more) {
            int nb = buf ^ 1;
            *(uint4*)(smt[nb][0] + sw_off) = pf0;
            *(uint4*)(smt[nb][1] + sw_off) = pf1;
            *(uint4*)(smt[nb][2] + sw_off) = pf2;
            *(uint4*)(smt[nb][3] + sw_off) = pf3;
        }
        __syncthreads();
        buf ^= 1;
    }

    // ---- epilogue ----
    const int row0 = lane >> 2, col0 = (lane & 3) * 2;
    #pragma unroll
    for (int i = 0; i < 4; ++i) {
        #pragma unroll
        for (int j = 0; j < 4; ++j) {
            int gi = bi * 128 + wm * 64 + i * 16 + row0;
            int gj = bj * 128 + wn * 32 + j * 8 + col0;
            *(float2*)(g_C + (size_t)gi * Dn + gj) =
                make_float2(acc[i][j][0], acc[i][j][1]);
            *(float2*)(g_C + (size_t)(gi + 8) * Dn + gj) =
                make_float2(acc[i][j][2], acc[i][j][3]);
            if (bi != bj) {
                g_C[(size_t)gj * Dn + gi]           = acc[i][j][0];
                g_C[(size_t)(gj + 1) * Dn + gi]     = acc[i][j][1];
                g_C[(size_t)gj * Dn + gi + 8]       = acc[i][j][2];
                g_C[(size_t)(gj + 1) * Dn + gi + 8] = acc[i][j][3];
            }
        }
    }
}

// ---------------- persistent sequential CCIPCA solve (exact R3 form) ----------
__global__ void __launch_bounds__(256) solve_kernel() {
    extern __shared__ __align__(16) float s_dyn[];
    float* s_C   = s_dyn;
    float* s_WT  = s_dyn + ROWS_PB * Dn;
    float* s_VnT = s_dyn + ROWS_PB * Dn + ROWS_PB * Kn;
    __shared__ __align__(16) float s_a[Dn];
    __shared__ float sc3s[Kn], sc1[Kn], s_g[Kn];
    __shared__ float s_b[16], s_u[16], s_vk1[16];

    const int tid = threadIdx.x;
    const int bid = blockIdx.x;
    const int wid = tid >> 5, lane = tid & 31;
    int d_lo = bid * ROWS_PB; if (d_lo > Dn) d_lo = Dn;
    int d_hi = d_lo + ROWS_PB; if (d_hi > Dn) d_hi = Dn;
    const int nrows = d_hi - d_lo;
    unsigned gen = 0;

    {
        const float4* src = (const float4*)&g_C[(size_t)d_lo * Dn];
        float4* dst = (float4*)s_C;
        for (int i = tid; i < nrows * (Dn / 4); i += 256) dst[i] = src[i];
    }
    __syncthreads();

    for (int k = 0; k < Kn; ++k) {
        const int pin = k & 1, pout = pin ^ 1;

        float s = 0.f, c1k1 = 0.f;
        if (k > 0) {
            s = rsqrtf(g_dn2[pin]);
            c1k1 = s * g_uv[pin];
            for (int j = tid; j < k - 1; j += 256) {
                sc3s[j] = g_c3[pin][j] * s;
                sc1[j]  = g_c1[pin][j];
            }
        }
        if (bid == 0) {
            for (int j = tid; j < Kn; j += 256) {
                g_c3[pout][j] = 0.f;
                g_c1[pout][j] = 0.f;
                g_g[j] = 0.f;
            }
            if (tid == 0) { g_dn2[pout] = 0.f; g_uv[pout] = 0.f; }
        }
        __syncthreads();

        if (k == 0) {
            for (int d = d_lo + tid; d < d_hi; d += 256)
                g_a[d] = g_Vt[d];
        } else {
            for (int dd = wid; dd < nrows; dd += 8) {
                int d = d_lo + dd;
                float u_d = s_u[dd];
                const float* wrow = &s_WT[dd * Kn];
                float sum1 = 0.f, sum2 = 0.f;
                #pragma unroll 4
                for (int j = lane; j < k - 1; j += 32) {
                    float wj = wrow[j];
                    sum1 += sc3s[j] * wj;
                    sum2 += sc1[j] * wj;
                }
                #pragma unroll
                for (int o = 16; o; o >>= 1) {
                    sum1 += __shfl_down_sync(~0u, sum1, o);
                    sum2 += __shfl_down_sync(~0u, sum2, o);
                }
                if (lane == 0) {
                    float vn_d = s * u_d;
                    float w_d = vn_d - sum1;
                    s_VnT[dd * Kn + (k - 1)] = vn_d;
                    g_VnT[(size_t)d * Kn + (k - 1)] = vn_d;
                    s_WT[dd * Kn + (k - 1)] = w_d;
                    g_a[d] = g_Vt[(size_t)k * Dn + d] - sum2 - c1k1 * w_d;
                }
            }
        }
        gbar(gen);

        for (int i = tid; i < Dn / 4; i += 256)
            ((float4*)s_a)[i] = ((const float4*)g_a)[i];
        __syncthreads();
        for (int dd = wid; dd < nrows; dd += 8) {
            const float4* crow = (const float4*)&s_C[dd * Dn];
            float sum = 0.f;
            #pragma unroll 4
            for (int t = lane; t < Dn / 4; t += 32) {
                float4 c4 = crow[t];
                float4 a4 = ((const float4*)s_a)[t];
                sum += c4.x * a4.x + c4.y * a4.y + c4.z * a4.z + c4.w * a4.w;
            }
            #pragma unroll
            for (int o = 16; o; o >>= 1) sum += __shfl_down_sync(~0u, sum, o);
            if (lane == 0) s_b[dd] = sum;
        }
        __syncthreads();
        if (tid < k && nrows > 0) {
            float accg = 0.f;
            #pragma unroll 7
            for (int dd = 0; dd < nrows; ++dd)
                accg += s_WT[dd * Kn + tid] * s_b[dd];
            atomicAdd(&g_g[tid], accg);
        }
        gbar(gen);

        const float hh = 0.5f / g_d0[k];
        for (int j = tid; j < k; j += 256) s_g[j] = g_g[j];
        __syncthreads();
        for (int dd = wid; dd < nrows; dd += 8) {
            int d = d_lo + dd;
            const float* vrow = &s_VnT[dd * Kn];
            float sumg = 0.f;
            #pragma unroll 4
            for (int j = lane; j < k; j += 32) sumg += s_g[j] * vrow[j];
            #pragma unroll
            for (int o = 16; o; o >>= 1) sumg += __shfl_down_sync(~0u, sumg, o);
            if (lane == 0) {
                float u_d = 0.5f * g_Vt[(size_t)k * Dn + d] + hh * (s_b[dd] - sumg);
                s_u[dd] = u_d;
                s_vk1[dd] = (k + 1 < Kn) ? g_Vt[(size_t)(k + 1) * Dn + d] : 0.f;
            }
        }
        __syncthreads();
        if (tid < k && nrows > 0) {
            float a3 = 0.f, a1 = 0.f;
            #pragma unroll 7
            for (int dd = 0; dd < nrows; ++dd) {
                float vv = s_VnT[dd * Kn + tid];
                a3 += vv * s_u[dd];
                a1 += vv * s_vk1[dd];
            }
            atomicAdd(&g_c3[pout][tid], a3);
            atomicAdd(&g_c1[pout][tid], a1);
        }
        if (tid == 0 && nrows > 0) {
            float d2 = 0.f, uvv = 0.f;
            #pragma unroll 7
            for (int dd = 0; dd < nrows; ++dd) {
                d2  += s_u[dd] * s_u[dd];
                uvv += s_u[dd] * s_vk1[dd];
            }
            atomicAdd(&g_dn2[pout], d2);
            atomicAdd(&g_uv[pout], uvv);
        }
        gbar(gen);
    }

    {
        const int plast = ((Kn - 1) & 1) ^ 1;
        float sfin = rsqrtf(g_dn2[plast]);
        for (int dd = tid; dd < nrows; dd += 256)
            g_VnT[(size_t)(d_lo + dd) * Kn + (Kn - 1)] = sfin * s_u[dd];
    }

    __syncthreads();
    if (tid == 0) {
        __threadfence();
        if (atomicAdd(&g_done, 1u) == (unsigned)(gridDim.x - 1)) {
            g_done = 0u;
            g_barcnt = 0u;
            __threadfence();
        }
    }
}

// ---------------- out = x @ VnT (double-buffered, f32x2) ----------------
__global__ void __launch_bounds__(256) gemmOut_kernel(const float* __restrict__ x,
                                                      float* __restrict__ out) {
    __shared__ __align__(16) float As[2][16][132];
    __shared__ __align__(16) float Bs[2][16][64];

    const int br = blockIdx.x >> 2;
    const int bc = blockIdx.x & 3;
    const int tid = threadIdx.x;
    const int ty = tid >> 4, tx = tid & 15;
    const int n0 = br * 128;

    ull acc2[8][2];
    const ull z = splat2(0.f);
    #pragma unroll
    for (int p = 0; p < 8; ++p) { acc2[p][0] = z; acc2[p][1] = z; }

    const int ra0 = tid >> 2, ca0 = tid & 3;
    const int ra1 = (tid + 256) >> 2, ca1 = tid & 3;
    const int rb = tid >> 4, cb = tid & 15;

    float4 va0, va1, vb;
    auto stage = [&](int b) {
        As[b][ca0 * 4 + 0][ra0] = va0.x;
        As[b][ca0 * 4 + 1][ra0] = va0.y;
        As[b][ca0 * 4 + 2][ra0] = va0.z;
        As[b][ca0 * 4 + 3][ra0] = va0.w;
        As[b][ca1 * 4 + 0][ra1] = va1.x;
        As[b][ca1 * 4 + 1][ra1] = va1.y;
        As[b][ca1 * 4 + 2][ra1] = va1.z;
        As[b][ca1 * 4 + 3][ra1] = va1.w;
        ((float4*)&Bs[b][rb][0])[cb] = vb;
    };

    va0 = *(const float4*)(x + (size_t)(n0 + ra0) * Dn + ca0 * 4);
    va1 = *(const float4*)(x + (size_t)(n0 + ra1) * Dn + ca1 * 4);
    vb  = *(const float4*)(&g_VnT[(size_t)rb * Kn + bc * 64 + cb * 4]);
    stage(0);

    int buf = 0;
    for (int dchunk = 0; dchunk < Dn; dchunk += 16) {
        __syncthreads();
        const bool more = (dchunk + 16 < Dn);
        if (more) {
            int dn = dchunk + 16;
            va0 = *(const float4*)(x + (size_t)(n0 + ra0) * Dn + dn + ca0 * 4);
            va1 = *(const float4*)(x + (size_t)(n0 + ra1) * Dn + dn + ca1 * 4);
            vb  = *(const float4*)(&g_VnT[(size_t)(dn + rb) * Kn + bc * 64 + cb * 4]);
        }
        #pragma unroll
        for (int kk = 0; kk < 16; ++kk) {
            float a8[8];
            *(float4*)&a8[0] = *(const float4*)&As[buf][kk][ty * 8];
            *(float4*)&a8[4] = *(const float4*)&As[buf][kk][ty * 8 + 4];
            const ull* bp = (const ull*)&Bs[buf][kk][tx * 4];
            ull b2[2] = { bp[0], bp[1] };
            #pragma unroll
            for (int p = 0; p < 8; ++p) {
                ull ap = splat2(a8[p]);
                fma2(acc2[p][0], ap, b2[0]);
                fma2(acc2[p][1], ap, b2[1]);
            }
        }
        if (more) stage(buf ^ 1);
        buf ^= 1;
    }

    #pragma unroll
    for (int p = 0; p < 8; ++p) {
        float2 v0 = *(float2*)&acc2[p][0];
        float2 v1 = *(float2*)&acc2[p][1];
        *(float4*)(out + (size_t)(n0 + ty * 8 + p) * Kn + bc * 64 + tx * 4) =
            make_float4(v0.x, v0.y, v1.x, v1.y);
    }
}

// ---------------- launch ----------------
extern "C" void kernel_launch(void* const* d_in, const int* in_sizes, int n_in,
                              void* d_out, int out_size) {
    const float* x  = (const float*)d_in[0];
    const float* V0 = (const float*)d_in[1];
    if (n_in >= 2 && in_sizes[0] == Dn * Kn && in_sizes[1] == Nn * Dn) {
        const float* t = x; x = V0; V0 = t;
    }
    float* out = (float*)d_out;

    static int smem_set = 0;
    const int dyn_smem = (ROWS_PB * Dn + 2 * ROWS_PB * Kn) * (int)sizeof(float); // 143360
    if (!smem_set) {
        cudaFuncSetAttribute(solve_kernel,
                             cudaFuncAttributeMaxDynamicSharedMemorySize, dyn_smem);
        smem_set = 1;
    }

    splitx_kernel<<<2048, 256>>>(x);
    prep_kernel<<<Kn, 256>>>(V0);
    gemmC_tc_kernel<<<136, 256>>>();
    solve_kernel<<<NBLK, 256, dyn_smem>>>();
    gemmOut_kernel<<<256, 256>>>(x, out);
}